// round 5
// baseline (speedup 1.0000x reference)
#include <cuda_runtime.h>
#include <math.h>

// Problem shape constants (fixed by the dataset).
#define BATCH 64
#define NCLS  10
#define NDIR  4
#define CHW   16384     // C*H*W = 64*16*16
#define FCHW  32768     // F*C*H*W, F=2
#define EPSV  1e-6f

// ---------------- device scratch (no allocations allowed) ----------------
__device__ float g_xbins[NCLS * FCHW];   // x_bins, (NC, F, C, H, W)
__device__ float g_mt[NCLS * CHW];       // means_theta
__device__ float g_lmm[NCLS * CHW];      // log(means_mag + eps)
__device__ float g_norm[NDIR * NCLS];    // norm[d][c] accumulators
__device__ float g_cnt[NCLS];
__device__ float g_invcnt[NCLS];
__device__ int   g_order[BATCH];         // b indices grouped by class
__device__ int   g_start[NCLS + 1];      // class segment starts into g_order
__device__ float g_rt[NCLS * NDIR];      // tao^2/(sig^2+tao^2)
__device__ float g_rs[NCLS * NDIR];      // sig^2/(sig^2+tao^2)
__device__ float g_w1n[NDIR];            // w1^2/sum(w1^2)  (reference uses w1 for BOTH w1n and w2n)
__device__ float g_w0sq, g_w1sq;

// jax.nn.log_sigmoid(x) = -softplus(-x), numerically stable form
__device__ __forceinline__ float lsig(float x) {
    return fminf(x, 0.f) - log1pf(expf(-fabsf(x)));
}

// ---------------- K0: scalar prep (single thread) ----------------
__global__ void k_init(const int* __restrict__ labels,
                       const float* __restrict__ w1,
                       const float* __restrict__ tao,
                       const float* __restrict__ weight,
                       const float* __restrict__ sigmas,
                       const float* __restrict__ Xw) {
    int hist[NCLS];
#pragma unroll
    for (int c = 0; c < NCLS; c++) hist[c] = 0;
    for (int b = 0; b < BATCH; b++) hist[labels[b]]++;
    int pos = 0;
    for (int c = 0; c < NCLS; c++) {
        g_start[c] = pos;
        for (int b = 0; b < BATCH; b++)
            if (labels[b] == c) g_order[pos++] = b;
    }
    g_start[NCLS] = pos;
    for (int c = 0; c < NCLS; c++) {
        float cnt = Xw[c] + (float)hist[c];
        g_cnt[c] = cnt;
        g_invcnt[c] = 1.f / cnt;
    }
    float s1 = 0.f;
    for (int d = 0; d < NDIR; d++) s1 += w1[d] * w1[d];
    for (int d = 0; d < NDIR; d++) g_w1n[d] = w1[d] * w1[d] / s1;
    for (int c = 0; c < NCLS; c++) {
        float s2 = sigmas[c] * sigmas[c];
        for (int d = 0; d < NDIR; d++) {
            float t2 = tao[d] * tao[d];
            g_rt[c * NDIR + d] = t2 / (s2 + t2);
            g_rs[c * NDIR + d] = s2 / (s2 + t2);
        }
    }
    g_w0sq = weight[0] * weight[0];
    g_w1sq = weight[1] * weight[1];
    for (int k = 0; k < NDIR * NCLS; k++) g_norm[k] = 0.f;  // reset every launch (graph replays)
}

// ---------------- K1: segment means + loss norm ----------------
// One thread per flat (f,c,h,w) position. Reads x_LE once (via per-class order),
// writes x_bins, accumulates norm[d][c] via warp reduce + atomicAdd.
__global__ void k1_bins(const float* __restrict__ xle,
                        const float* __restrict__ XLEs,
                        const float* __restrict__ miu) {
    __shared__ int   s_order[BATCH];
    __shared__ int   s_start[NCLS + 1];
    __shared__ float s_inv[NCLS];
    int t = threadIdx.x;
    if (t < BATCH) s_order[t] = g_order[t];
    if (t <= NCLS) s_start[t] = g_start[t];
    if (t < NCLS)  s_inv[t]   = g_invcnt[t];
    __syncthreads();

    int idx = blockIdx.x * blockDim.x + t;   // < FCHW
    float lsm[NDIR];
#pragma unroll
    for (int d = 0; d < NDIR; d++) lsm[d] = lsig(miu[d * FCHW + idx]);

    int lane = t & 31;
    for (int c = 0; c < NCLS; c++) {
        float s = 0.f;
        int e = s_start[c + 1];
        for (int j = s_start[c]; j < e; j++)
            s += xle[s_order[j] * FCHW + idx];
        float xb = (XLEs[c * FCHW + idx] + s) * s_inv[c];
        g_xbins[c * FCHW + idx] = xb;
        float lx = lsig(xb);
#pragma unroll
        for (int d = 0; d < NDIR; d++) {
            float df = lx - lsm[d];
            float v = df * df;
#pragma unroll
            for (int o = 16; o > 0; o >>= 1) v += __shfl_down_sync(0xffffffffu, v, o);
            if (lane == 0) atomicAdd(&g_norm[d * NCLS + c], v);
        }
    }
}

// ---------------- K2: means_theta + log(means_mag+eps) ----------------
__global__ void k2_means(const float* __restrict__ miu) {
    int tid = blockIdx.x * blockDim.x + threadIdx.x;   // < NCLS*CHW
    int c   = tid >> 14;
    int chw = tid & (CHW - 1);
    float mag  = g_xbins[c * FCHW + CHW + chw];        // x_bins[c, f=1, chw]
    float lmag = lsig(mag + EPSV);
    float mm = 0.f, mt = 0.f;
#pragma unroll
    for (int d = 0; d < NDIR; d++) {
        float m0 = miu[d * FCHW + chw];                // miu[d, f=0]
        float m1 = miu[d * FCHW + CHW + chw];          // miu[d, f=1]
        float rt = g_rt[c * NDIR + d];
        float rs = g_rs[c * NDIR + d];
        float w  = g_w1n[d];                           // w2n == w1n in reference
        mm += expf((rt * lmag + rs * lsig(m1 + EPSV)) * w);
        mt += (mag * rt + m0 * rs) * w;
    }
    g_mt[c * CHW + chw]  = mt;
    g_lmm[c * CHW + chw] = logf(mm + EPSV);
}

// ---------------- K3: x_out = min_c dist ----------------
__global__ void k3_xout(const float* __restrict__ xle, float* __restrict__ out) {
    int tid = blockIdx.x * blockDim.x + threadIdx.x;   // < BATCH*CHW
    int b   = tid >> 14;
    int chw = tid & (CHW - 1);
    float x0  = xle[b * FCHW + chw];                   // x_LE[b, f=0]
    float lx1 = logf(xle[b * FCHW + CHW + chw]);       // log x_LE[b, f=1]
    float w0 = g_w0sq, w1 = g_w1sq;
    float best = 3.402823466e38f;
#pragma unroll
    for (int c = 0; c < NCLS; c++) {
        float dr = fabsf(x0  - g_mt[c * CHW + chw]);
        float da = fabsf(lx1 - g_lmm[c * CHW + chw]);
        best = fminf(best, fmaf(w0, dr, w1 * da));
    }
    out[tid] = best;
}

// ---------------- K4: loss finalize ----------------
__global__ void k4_loss(const float* __restrict__ tao,
                        const float* __restrict__ sigmas,
                        float* __restrict__ out) {
    __shared__ float sv[NDIR * NCLS];
    int t = threadIdx.x;
    if (t < NDIR * NCLS) {
        int d = t / NCLS, c = t % NCLS;
        float t2 = tao[d] * tao[d];
        float s2 = sigmas[c] * sigmas[c];
        float term1 = s2 / ((t2 + s2) * (t2 + s2));
        float term2 = s2 * g_norm[d * NCLS + c];
        float term3 = 2.f * (float)CHW * (t2 * t2 - s2 * s2) / g_cnt[c];
        sv[t] = term1 * (term2 + term3);
    }
    __syncthreads();
    if (t < NDIR) {
        float s = 0.f;
        for (int c = 0; c < NCLS; c++) s += sv[t * NCLS + c];
        out[BATCH * CHW + t] = s * (1.f / NCLS);
    }
}

extern "C" void kernel_launch(void* const* d_in, const int* in_sizes, int n_in,
                              void* d_out, int out_size) {
    const float* xle    = (const float*)d_in[0];   // x_LE    (64,2,64,16,16)
    const int*   labels = (const int*)  d_in[1];   // labels  (64,)
    const float* w1     = (const float*)d_in[2];   // w1      (4,)
    // d_in[3] = w2 (unused by reference math: w2n is computed from w1)
    const float* miu    = (const float*)d_in[4];   // miu     (4,2,64,16,16)
    const float* tao    = (const float*)d_in[5];   // tao     (4,)
    const float* weight = (const float*)d_in[6];   // weight  (2,)
    const float* sigmas = (const float*)d_in[7];   // sigmas  (10,)
    const float* XLEs   = (const float*)d_in[8];   // X_LEs   (10,2,64,16,16)
    const float* Xw     = (const float*)d_in[9];   // X_weights (10,1)
    float* out = (float*)d_out;                    // [x_out (64*16384) | loss (4)]

    k_init<<<1, 1>>>(labels, w1, tao, weight, sigmas, Xw);
    k1_bins<<<FCHW / 256, 256>>>(xle, XLEs, miu);
    k2_means<<<(NCLS * CHW) / 256, 256>>>(miu);
    k3_xout<<<(BATCH * CHW) / 256, 256>>>(xle, out);
    k4_loss<<<1, 64>>>(tao, sigmas, out);
}

// round 9
// speedup vs baseline: 2.8764x; 2.8764x over previous
#include <cuda_runtime.h>
#include <math.h>

#define BATCH 64
#define NCLS  10
#define NDIR  4
#define CHW   16384     // C*H*W
#define FCHW  32768     // F*C*H*W, F=2
#define EPSV  1e-6f
#define NK    40        // NDIR*NCLS
#define K1BLK 128       // FCHW/256

// ---------------- device scratch ----------------
__device__ float g_mt[NCLS * CHW];        // means_theta
__device__ float g_lmm[NCLS * CHW];       // log(means_mag + eps)
__device__ float g_pnorm[K1BLK * NK];     // per-block partial norm[d*10+c]

// log_sigmoid, fast-math variant (args here are O(1), no log1p edge case)
__device__ __forceinline__ float lsig(float x) {
    return fminf(x, 0.f) - __logf(1.f + __expf(-fabsf(x)));
}

// =======================================================================
// K1: fused segment-mean + loss-norm partials + means tables.
// One thread per (f,chw) flat index. Each block self-initializes the tiny
// label ordering + rt/rs/w tables in shared memory (no separate init kernel).
// =======================================================================
__global__ __launch_bounds__(256) void k1_fused(
    const float* __restrict__ xle,
    const float* __restrict__ XLEs,
    const float* __restrict__ miu,
    const int*   __restrict__ labels,
    const float* __restrict__ w1,
    const float* __restrict__ tao,
    const float* __restrict__ sigmas,
    const float* __restrict__ Xw)
{
    __shared__ int   s_lab[BATCH];
    __shared__ int   s_hist[NCLS];
    __shared__ int   s_start[NCLS + 1];
    __shared__ int   s_order[BATCH];
    __shared__ float s_inv[NCLS];
    __shared__ float s_rt[NCLS * NDIR];
    __shared__ float s_rs[NCLS * NDIR];
    __shared__ float s_w[NDIR];
    __shared__ float s_red[(256 + 6) * 41];   // padded (stride 41) reduction tile

    const int t = threadIdx.x;

    // ---- block-local prep ----
    if (t < BATCH) s_lab[t] = labels[t];
    if (t < NCLS)  s_hist[t] = 0;
    if (t >= 128 && t < 128 + NK) {          // rt/rs tables (indep. of labels)
        int k = t - 128, c = k >> 2, d = k & 3;
        float s2 = sigmas[c] * sigmas[c];
        float t2 = tao[d] * tao[d];
        float inv = 1.f / (s2 + t2);
        s_rt[k] = t2 * inv;
        s_rs[k] = s2 * inv;
    }
    if (t >= 192 && t < 196) {
        int d = t - 192;
        float a = w1[0]*w1[0], b = w1[1]*w1[1], c = w1[2]*w1[2], e = w1[3]*w1[3];
        s_w[d] = (w1[d]*w1[d]) / (a + b + c + e);
    }
    __syncthreads();
    if (t < BATCH) atomicAdd(&s_hist[s_lab[t]], 1);
    __syncthreads();
    if (t == 0) {
        int p = 0;
        for (int c = 0; c < NCLS; c++) { s_start[c] = p; p += s_hist[c]; }
        s_start[NCLS] = p;
    }
    if (t < NCLS) s_inv[t] = 1.f / (Xw[t] + (float)s_hist[t]);
    __syncthreads();
    if (t < BATCH) {            // stable rank within class
        int lab = s_lab[t], r = 0;
        for (int j = 0; j < t; j++) r += (s_lab[j] == lab);
        s_order[s_start[lab] + r] = t;
    }
    __syncthreads();

    // ---- main body ----
    const int  idx = blockIdx.x * 256 + t;        // < FCHW
    const bool f1  = (idx >= CHW);
    const int  chw = idx - CHW;

    float lsm[NDIR], lsme[NDIR], miu0[NDIR];
#pragma unroll
    for (int d = 0; d < NDIR; d++) {
        float m = miu[d * FCHW + idx];
        lsm[d] = lsig(m);
        if (f1) {
            lsme[d] = lsig(m + EPSV);                 // ls(miu[:,1]+eps)
            miu0[d] = miu[d * FCHW + chw];            // miu[:,0]
        }
    }

    float acc[NK];
#pragma unroll
    for (int k = 0; k < NK; k++) acc[k] = 0.f;

#pragma unroll
    for (int c = 0; c < NCLS; c++) {
        float s = 0.f;
        const int j1 = s_start[c + 1];
        for (int j = s_start[c]; j < j1; j++)
            s += xle[s_order[j] * FCHW + idx];
        const float xb = (XLEs[c * FCHW + idx] + s) * s_inv[c];
        const float lx = lsig(xb);
#pragma unroll
        for (int d = 0; d < NDIR; d++) {
            float df = lx - lsm[d];
            acc[d * NCLS + c] = fmaf(df, df, acc[d * NCLS + c]);
        }
        if (f1) {   // fused means (old k2): mag = x_bins[c, f=1, chw] = xb
            float lmag = lsig(xb + EPSV);
            float mm = 0.f, mt = 0.f;
#pragma unroll
            for (int d = 0; d < NDIR; d++) {
                float rt = s_rt[c * 4 + d], rs = s_rs[c * 4 + d], w = s_w[d];
                mm += __expf((rt * lmag + rs * lsme[d]) * w);
                mt += (xb * rt + miu0[d] * rs) * w;
            }
            g_mt [c * CHW + chw] = mt;
            g_lmm[c * CHW + chw] = __logf(mm + EPSV);
        }
    }

    // ---- block reduce of acc[40], no atomics ----
#pragma unroll
    for (int k = 0; k < NK; k++) s_red[t * 41 + k] = acc[k];
    __syncthreads();
    if (t < 240) {                      // 6 partial rows x 40 cols
        int p = t / NK, k = t - p * NK;
        float s = 0.f;
        for (int r = p; r < 256; r += 6) s += s_red[r * 41 + k];
        s_red[(256 + p) * 41 + k] = s;
    }
    __syncthreads();
    if (t < NK) {
        float s = 0.f;
#pragma unroll
        for (int p = 0; p < 6; p++) s += s_red[(256 + p) * 41 + t];
        g_pnorm[blockIdx.x * NK + t] = s;
    }
}

// =======================================================================
// K2: vectorized x_out (blocks 0..1023) + loss finalize (block 1024)
// =======================================================================
__global__ __launch_bounds__(256) void k2_out(
    const float* __restrict__ xle,
    const float* __restrict__ weight,
    const int*   __restrict__ labels,
    const float* __restrict__ tao,
    const float* __restrict__ sigmas,
    const float* __restrict__ Xw,
    float* __restrict__ out)
{
    const int t = threadIdx.x;
    if (blockIdx.x < 1024) {
        const int tid = blockIdx.x * 256 + t;     // < BATCH*CHW/4
        const int b = tid >> 12;                  // CHW/4 = 4096 float4 per b
        const int q = tid & 4095;
        const float4* x4 = (const float4*)xle;
        float4 x0 = x4[b * 8192 + q];             // x_LE[b, f=0]
        float4 x1 = x4[b * 8192 + 4096 + q];      // x_LE[b, f=1]
        const float w0 = weight[0] * weight[0];
        const float w1 = weight[1] * weight[1];
        float l0 = __logf(x1.x), l1 = __logf(x1.y), l2 = __logf(x1.z), l3 = __logf(x1.w);
        float4 best = make_float4(3.4e38f, 3.4e38f, 3.4e38f, 3.4e38f);
        const float4* mt4  = (const float4*)g_mt;
        const float4* lmm4 = (const float4*)g_lmm;
#pragma unroll
        for (int c = 0; c < NCLS; c++) {
            float4 mt = mt4 [c * 4096 + q];
            float4 lm = lmm4[c * 4096 + q];
            best.x = fminf(best.x, fmaf(w0, fabsf(x0.x - mt.x), w1 * fabsf(l0 - lm.x)));
            best.y = fminf(best.y, fmaf(w0, fabsf(x0.y - mt.y), w1 * fabsf(l1 - lm.y)));
            best.z = fminf(best.z, fmaf(w0, fabsf(x0.z - mt.z), w1 * fabsf(l2 - lm.z)));
            best.w = fminf(best.w, fmaf(w0, fabsf(x0.w - mt.w), w1 * fabsf(l3 - lm.w)));
        }
        ((float4*)out)[tid] = best;
    } else {
        // ---- loss block ----
        __shared__ int   s_lab[BATCH];
        __shared__ int   s_hist[NCLS];
        __shared__ float s_norm[NK];
        __shared__ float sv[NK];
        if (t < BATCH) s_lab[t] = labels[t];
        if (t < NCLS)  s_hist[t] = 0;
        __syncthreads();
        if (t < BATCH) atomicAdd(&s_hist[s_lab[t]], 1);
        if (t < NK) {
            float s = 0.f;
            for (int p = 0; p < K1BLK; p++) s += g_pnorm[p * NK + t];
            s_norm[t] = s;
        }
        __syncthreads();
        if (t < NK) {
            int d = t / NCLS, c = t - d * NCLS;
            float t2 = tao[d] * tao[d];
            float s2 = sigmas[c] * sigmas[c];
            float cnt = Xw[c] + (float)s_hist[c];
            float term1 = s2 / ((t2 + s2) * (t2 + s2));
            float term2 = s2 * s_norm[t];
            float term3 = 2.f * (float)CHW * (t2 * t2 - s2 * s2) / cnt;
            sv[t] = term1 * (term2 + term3);
        }
        __syncthreads();
        if (t < NDIR) {
            float s = 0.f;
#pragma unroll
            for (int c = 0; c < NCLS; c++) s += sv[t * NCLS + c];
            out[BATCH * CHW + t] = s * (1.f / NCLS);
        }
    }
}

extern "C" void kernel_launch(void* const* d_in, const int* in_sizes, int n_in,
                              void* d_out, int out_size) {
    const float* xle    = (const float*)d_in[0];   // x_LE    (64,2,64,16,16)
    const int*   labels = (const int*)  d_in[1];   // labels  (64,)
    const float* w1     = (const float*)d_in[2];   // w1      (4,)
    // d_in[3] = w2 (unused: reference computes w2n from w1)
    const float* miu    = (const float*)d_in[4];   // miu     (4,2,64,16,16)
    const float* tao    = (const float*)d_in[5];   // tao     (4,)
    const float* weight = (const float*)d_in[6];   // weight  (2,)
    const float* sigmas = (const float*)d_in[7];   // sigmas  (10,)
    const float* XLEs   = (const float*)d_in[8];   // X_LEs   (10,2,64,16,16)
    const float* Xw     = (const float*)d_in[9];   // X_weights (10,1)
    float* out = (float*)d_out;                    // [x_out (64*16384) | loss (4)]

    k1_fused<<<K1BLK, 256>>>(xle, XLEs, miu, labels, w1, tao, sigmas, Xw);
    k2_out<<<1025, 256>>>(xle, weight, labels, tao, sigmas, Xw, out);
}